// round 15
// baseline (speedup 1.0000x reference)
#include <cuda_runtime.h>
#include <cuda_bf16.h>
#include <cstdint>

typedef unsigned long long u64;
typedef unsigned int u32;

// Shapes (fixed): imgs (32,3,512,512) f32; weight (512,16384) f32; bias (512);
// out (32,512) f32.
#define BATCH    32
#define NDIM     512
#define KDIM     16384
#define KSPLIT   32         // GEMM grid.y
#define KCHUNK   512        // k per CTA (32 k16 groups)
#define KSTAGE   64         // k per W pipeline stage (4 k16)
#define NSTAGES  8
#define MTILE    128        // W rows per CTA

// A smem: bf16, fragment-paired chunks. Per row per k16: 32B chunk where the
// 8B at tg*8 = {pair(k0+2tg), pair(k8+2tg)} = mma (a0, a2) operands.
#define AROW   160                      // bytes per row (128 data + 32 pad)
#define ABUF   (MTILE * AROW)           // 20480 B  per plane per buffer
#define SMEM_A (2 * 2 * ABUF)           // hi/lo x double buffer = 81920
// B smem: same chunk layout, whole 512-k chunk resident. 32 k16 * 32B + pad.
#define BROW   1056                     // 1024 + 32 pad
#define SMEM_B (2 * BATCH * BROW)       // hi/lo = 67584
#define SMEM_BYTES (SMEM_A + SMEM_B)    // 149504

// Device scratch (no allocation allowed anywhere). Feats stored as B-layout
// planes: per batch 1024 k16-chunks of 32B (chunk = paired-pack of 16 k).
__device__ __align__(256) unsigned char g_fBh[BATCH * 32768];  // 1 MB hi
__device__ __align__(256) unsigned char g_fBl[BATCH * 32768];  // 1 MB lo
__device__ float g_part[KSPLIT * NDIM * BATCH];                // 2 MB [ks][nout][b]

// ---------------------------------------------------------------------------
// PTX helpers (baseline features only — compute_103 virtual arch, no 'a')
// ---------------------------------------------------------------------------
__device__ __forceinline__ void cp16(void* dst, const void* src) {
    u32 d = (u32)__cvta_generic_to_shared(dst);
    asm volatile("cp.async.ca.shared.global [%0], [%1], 16;\n"
                 :: "r"(d), "l"(src) : "memory");
}
__device__ __forceinline__ void cp_commit() {
    asm volatile("cp.async.commit_group;\n" ::: "memory");
}
template <int N> __device__ __forceinline__ void cp_wait() {
    asm volatile("cp.async.wait_group %0;\n" :: "n"(N) : "memory");
}
// pack two f32 -> bf16x2 reg {lo = v.x, hi = v.y} (round-to-nearest)
__device__ __forceinline__ u32 bf2hi(float x, float y) {
    u32 d;
    asm("cvt.rn.bf16x2.f32 %0, %1, %2;" : "=r"(d) : "f"(y), "f"(x));
    return d;
}
// residual (lo) pair given the hi pair
__device__ __forceinline__ u32 bf2lo(float x, float y, u32 h) {
    float h0 = __uint_as_float(h << 16);
    float h1 = __uint_as_float(h & 0xffff0000u);
    u32 d;
    asm("cvt.rn.bf16x2.f32 %0, %1, %2;" : "=r"(d) : "f"(y - h1), "f"(x - h0));
    return d;
}
__device__ __forceinline__ void mma16816(float* c, u32 a0, u32 a1, u32 a2, u32 a3,
                                         u32 b0, u32 b1) {
    asm volatile(
        "mma.sync.aligned.m16n8k16.row.col.f32.bf16.bf16.f32 "
        "{%0,%1,%2,%3}, {%4,%5,%6,%7}, {%8,%9}, {%0,%1,%2,%3};"
        : "+f"(c[0]), "+f"(c[1]), "+f"(c[2]), "+f"(c[3])
        : "r"(a0), "r"(a1), "r"(a2), "r"(a3), "r"(b0), "r"(b1));
}
__device__ __forceinline__ u32 lo32(u64 v) { return (u32)v; }
__device__ __forceinline__ u32 hi32(u64 v) { return (u32)(v >> 32); }

// ---------------------------------------------------------------------------
// Kernel 1: DCT features -> bf16 hi/lo planes in B-chunk layout.
// Only dct[0,0:4] survives:  s[l] = col-sums;  f_m = (1/8)*sum_l s[l]*cos(pi m l/4).
// 2 threads per 8x8 block (halves combined via shfl_xor(1)). k for block ij is
// 4*ij + m; within k16 chunk G=ij>>2, the pair (f0,f1) goes to paired-slot
// j0=2c (c=ij&3) at byte a0 = (c&1)*16 + (c>>1)*4, and (f2,f3) at a0+8.
// half0 writes the hi plane, half1 the lo plane.
// ---------------------------------------------------------------------------
__global__ __launch_bounds__(256) void feats_kernel(const float* __restrict__ img)
{
    int tid  = blockIdx.x * 256 + threadIdx.x;   // 0 .. 262143
    int u    = tid >> 1;
    int half = tid & 1;
    int b    = u >> 12;
    int ij   = u & 4095;
    int i = ij >> 6, j = ij & 63;

    const float* p = img + (long)b * 786432 + (long)(i * 8) * 512 + j * 8 + half * 4;

    float q0 = 0.f, q1 = 0.f, q2 = 0.f, q3 = 0.f;
#pragma unroll
    for (int r = 0; r < 8; r++) {
        float4 v = *(const float4*)(p + r * 512);
        q0 += v.x; q1 += v.y; q2 += v.z; q3 += v.w;
    }
    float c0 = (q0 + q1) + (q2 + q3);   // partial sum
    float c1 = q0;                       // s0 / s4
    float c2 = q1 - q3;                  // (s1-s3) / (s5-s7)
    float c3 = q0 - q2;                  // (s0-s2) / (s4-s6)

    float o0 = __shfl_xor_sync(0xffffffffu, c0, 1);
    float o1 = __shfl_xor_sync(0xffffffffu, c1, 1);
    float o2 = __shfl_xor_sync(0xffffffffu, c2, 1);
    float o3 = __shfl_xor_sync(0xffffffffu, c3, 1);

    float L0 = half ? o0 : c0, H0 = half ? c0 : o0;
    float L1 = half ? o1 : c1, H1 = half ? c1 : o1;
    float L2 = half ? o2 : c2, H2 = half ? c2 : o2;
    float L3 = half ? o3 : c3, H3 = half ? c3 : o3;

    const float R = 0.70710678118654752f;
    float e = L1 - H1;
    float o = L2 - H2;
    float f0 = 0.125f * (L0 + H0);
    float f1 = 0.125f * (e + R * o);
    float f2 = 0.125f * (L3 + H3);
    float f3 = 0.125f * (e - R * o);

    // hi pairs (both halves compute; each stores its own plane)
    u32 ph0 = bf2hi(f0, f1);
    u32 ph1 = bf2hi(f2, f3);

    int c  = ij & 3;
    long base = (long)b * 32768 + (long)(ij >> 2) * 32
              + (((c & 1) << 4) | ((c >> 1) << 2));
    if (half == 0) {
        *(u32*)(g_fBh + base)     = ph0;
        *(u32*)(g_fBh + base + 8) = ph1;
    } else {
        u32 pl0 = bf2lo(f0, f1, ph0);
        u32 pl1 = bf2lo(f2, f3, ph1);
        *(u32*)(g_fBl + base)     = pl0;
        *(u32*)(g_fBl + base + 8) = pl1;
    }
}

// ---------------------------------------------------------------------------
// Kernel 2: split-K GEMM on tensor cores (mma.sync m16n8k16 bf16).
//   D[512 nout, 32 b] = W @ feats^T via 3-term hi/lo split (err ~1e-5).
// grid (4 m-tiles, 32 k-splits), 256 threads, 1 CTA/SM.
// Per 64-k stage: W fp32 prefetched to regs (previous stage), converted to
// bf16 hi/lo PAIRED chunks in smem (off critical path), double-buffered.
// Inner loop per k16: 4 A-LDS.64 + 8 B-LDS.64 + 12 HMMA — nothing else.
// ---------------------------------------------------------------------------
__global__ __launch_bounds__(256, 1) void gemm_kernel(const float* __restrict__ W)
{
    extern __shared__ __align__(16) char sm[];
    char* Ah_base = sm;                       // [2][128][AROW] hi
    char* Al_base = sm + 2 * ABUF;            // [2][128][AROW] lo
    char* Bh      = sm + SMEM_A;              // [32][BROW] hi
    char* Bl      = sm + SMEM_A + BATCH * BROW;

    const int t  = threadIdx.x;
    const int w  = t >> 5, lid = t & 31;
    const int g  = lid >> 2, tg = lid & 3;
    const int mt = blockIdx.x, ks = blockIdx.y;
    const int wr = w * 16;

    const float* Wbase = W + (size_t)(mt * MTILE) * KDIM + ks * KCHUNK;

    // staging mapping: thread covers (row, c4): 4 floats = 2 pairs
    const int srow = t >> 1;                  // pairs with i*128 offset below
    // (we use idx = t + i*256 scheme: row = idx>>4, c4 = idx&15)

    // ---- B chunk cp.async (hi+lo, 32KB each) ----
#pragma unroll
    for (int i = 0; i < 8; i++) {
        int idx = t + i * 256;                // 0..2047
        int bb = idx >> 6, cc = idx & 63;     // batch row, 16B chunk
        long src = (long)bb * 32768 + (long)ks * 1024 + cc * 16;
        cp16(Bh + bb * BROW + cc * 16, g_fBh + src);
        cp16(Bl + bb * BROW + cc * 16, g_fBl + src);
    }
    cp_commit();

    // ---- prefetch W stage 0 ----
    float4 v[8];
#pragma unroll
    for (int i = 0; i < 8; i++) {
        int idx = t + i * 256;
        int row = idx >> 4, c4 = idx & 15;
        v[i] = *(const float4*)(Wbase + (size_t)row * KDIM + c4 * 4);
    }
    // ---- convert stage 0 -> buffer 0 ----
#pragma unroll
    for (int i = 0; i < 8; i++) {
        int idx = t + i * 256;
        int row = idx >> 4, c4 = idx & 15;
        int k16 = c4 >> 2, cc = c4 & 3;
        int off = row * AROW + k16 * 32 + (((cc & 1) << 4) | ((cc >> 1) << 2));
        u32 ph0 = bf2hi(v[i].x, v[i].y);
        u32 ph1 = bf2hi(v[i].z, v[i].w);
        *(u32*)(Ah_base + off)     = ph0;
        *(u32*)(Ah_base + off + 8) = ph1;
        *(u32*)(Al_base + off)     = bf2lo(v[i].x, v[i].y, ph0);
        *(u32*)(Al_base + off + 8) = bf2lo(v[i].z, v[i].w, ph1);
    }
    // ---- prefetch W stage 1 ----
#pragma unroll
    for (int i = 0; i < 8; i++) {
        int idx = t + i * 256;
        int row = idx >> 4, c4 = idx & 15;
        v[i] = *(const float4*)(Wbase + (size_t)row * KDIM + KSTAGE + c4 * 4);
    }
    cp_wait<0>();
    __syncthreads();

    float acc[4][4];
#pragma unroll
    for (int q = 0; q < 4; q++)
#pragma unroll
        for (int r = 0; r < 4; r++) acc[q][r] = 0.f;

    for (int s = 0; s < NSTAGES; s++) {
        const char* Ah = Ah_base + (s & 1) * ABUF;
        const char* Al = Al_base + (s & 1) * ABUF;

        // mma over this stage's 4 k16 groups
#pragma unroll
        for (int k16l = 0; k16l < 4; k16l++) {
            const int kk = s * 4 + k16l;      // global k16 within chunk
            const int ao = k16l * 32 + tg * 8;
            u64 ah0 = *(const u64*)(Ah + (wr + g)     * AROW + ao);
            u64 ah1 = *(const u64*)(Ah + (wr + g + 8) * AROW + ao);
            u64 al0 = *(const u64*)(Al + (wr + g)     * AROW + ao);
            u64 al1 = *(const u64*)(Al + (wr + g + 8) * AROW + ao);

#pragma unroll
            for (int q = 0; q < 4; q++) {
                const int bo = (q * 8 + g) * BROW + kk * 32 + tg * 8;
                u64 bh = *(const u64*)(Bh + bo);
                u64 bl = *(const u64*)(Bl + bo);
                // hi*hi, hi*lo, lo*hi
                mma16816(acc[q], lo32(ah0), lo32(ah1), hi32(ah0), hi32(ah1),
                         lo32(bh), hi32(bh));
                mma16816(acc[q], lo32(ah0), lo32(ah1), hi32(ah0), hi32(ah1),
                         lo32(bl), hi32(bl));
                mma16816(acc[q], lo32(al0), lo32(al1), hi32(al0), hi32(al1),
                         lo32(bh), hi32(bh));
            }
        }

        // convert stage s+1 (in regs) -> other buffer; prefetch stage s+2
        if (s + 1 < NSTAGES) {
            char* dAh = Ah_base + ((s + 1) & 1) * ABUF;
            char* dAl = Al_base + ((s + 1) & 1) * ABUF;
#pragma unroll
            for (int i = 0; i < 8; i++) {
                int idx = t + i * 256;
                int row = idx >> 4, c4 = idx & 15;
                int k16 = c4 >> 2, cc = c4 & 3;
                int off = row * AROW + k16 * 32 + (((cc & 1) << 4) | ((cc >> 1) << 2));
                u32 ph0 = bf2hi(v[i].x, v[i].y);
                u32 ph1 = bf2hi(v[i].z, v[i].w);
                *(u32*)(dAh + off)     = ph0;
                *(u32*)(dAh + off + 8) = ph1;
                *(u32*)(dAl + off)     = bf2lo(v[i].x, v[i].y, ph0);
                *(u32*)(dAl + off + 8) = bf2lo(v[i].z, v[i].w, ph1);
            }
            if (s + 2 < NSTAGES) {
                const float* Wn = Wbase + (size_t)(s + 2) * KSTAGE;
#pragma unroll
                for (int i = 0; i < 8; i++) {
                    int idx = t + i * 256;
                    int row = idx >> 4, c4 = idx & 15;
                    v[i] = *(const float4*)(Wn + (size_t)row * KDIM + c4 * 4);
                }
            }
        }
        __syncthreads();
    }

    // ---- epilogue: g_part[ks][nout][batch]; c0/c1, c2/c3 batch-adjacent ----
    float* op = g_part + (long)ks * (NDIM * BATCH);
    int nout = mt * MTILE + wr + g;
#pragma unroll
    for (int q = 0; q < 4; q++) {
        int bcol = q * 8 + tg * 2;
        *(float2*)&op[(long)nout * BATCH + bcol]       = make_float2(acc[q][0], acc[q][1]);
        *(float2*)&op[(long)(nout + 8) * BATCH + bcol] = make_float2(acc[q][2], acc[q][3]);
    }
    (void)srow;
}

// ---------------------------------------------------------------------------
// Kernel 3: single-stage split-K reduce (32 -> 1) + bias + transpose.
// 16384 threads; 8 independent accumulators (MLP), fixed order (deterministic).
// ---------------------------------------------------------------------------
__global__ __launch_bounds__(256) void reduce_kernel(const float* __restrict__ bias,
                                                     float* __restrict__ out)
{
    const int i = blockIdx.x * 256 + threadIdx.x;  // 0..16383 = nout*32 + b
    const int nout = i >> 5, b = i & 31;
    const int PL = NDIM * BATCH;

    float a0 = 0.f, a1 = 0.f, a2 = 0.f, a3 = 0.f;
    float a4 = 0.f, a5 = 0.f, a6 = 0.f, a7 = 0.f;
#pragma unroll
    for (int ks = 0; ks < KSPLIT; ks += 8) {
        a0 += g_part[(long)(ks + 0) * PL + i];
        a1 += g_part[(long)(ks + 1) * PL + i];
        a2 += g_part[(long)(ks + 2) * PL + i];
        a3 += g_part[(long)(ks + 3) * PL + i];
        a4 += g_part[(long)(ks + 4) * PL + i];
        a5 += g_part[(long)(ks + 5) * PL + i];
        a6 += g_part[(long)(ks + 6) * PL + i];
        a7 += g_part[(long)(ks + 7) * PL + i];
    }
    float s = (((a0 + a1) + (a2 + a3)) + ((a4 + a5) + (a6 + a7)));
    out[b * NDIM + nout] = s + bias[nout];
}

// ---------------------------------------------------------------------------
extern "C" void kernel_launch(void* const* d_in, const int* in_sizes, int n_in,
                              void* d_out, int out_size)
{
    const float* img    = (const float*)d_in[0];
    const float* weight = (const float*)d_in[1];
    const float* bias   = (const float*)d_in[2];
    float* out = (float*)d_out;

    cudaFuncSetAttribute(gemm_kernel,
                         cudaFuncAttributeMaxDynamicSharedMemorySize, SMEM_BYTES);

    feats_kernel<<<1024, 256>>>(img);
    gemm_kernel<<<dim3(4, KSPLIT), 256, SMEM_BYTES>>>(weight);
    reduce_kernel<<<(NDIM * BATCH) / 256, 256>>>(bias, out);
}